// round 16
// baseline (speedup 1.0000x reference)
#include <cuda_runtime.h>
#include <cstdint>

#define NN 50000
#define NE 800000
#define NGR 512
#define BN_EPS 1e-5f

// ---------------- scratch (static __device__ — no allocations) ----------------
__device__ float4 g_agg[NN * 16];
__device__ float4 g_z2 [NN * 16];
__device__ float  g_stats[384];          // 3 layers x (sum[64], sumsq[64])
__device__ float  g_pool[NGR * 64];      // raw z pool (pre-BN3)
__device__ int    g_gcnt[NGR];           // nodes per graph
__device__ int    g_deg[NN];
__device__ int    g_rowptr[NN + 1];
__device__ int    g_cursor[NN];
__device__ int    g_csr[NE];

// packed fp32x2 FMA (Blackwell family-level instruction, not an 'a' feature)
__device__ __forceinline__ void fma2(unsigned long long& acc,
                                     unsigned long long a,
                                     unsigned long long b) {
    asm("fma.rn.f32x2 %0, %1, %2, %0;" : "+l"(acc) : "l"(a), "l"(b));
}
__device__ __forceinline__ float fma2_reduce(unsigned long long acc) {
    float lo = __uint_as_float((uint32_t)acc);
    float hi = __uint_as_float((uint32_t)(acc >> 32));
    return lo + hi;
}
__device__ __forceinline__ void f4add(float4& a, float4 b) {
    a.x += b.x; a.y += b.y; a.z += b.z; a.w += b.w;
}

// ---------------- CSR build ----------------

__global__ void k_init(int* __restrict__ deg, float* __restrict__ stats,
                       float* __restrict__ pool, int* __restrict__ gcnt) {
    int i = blockIdx.x * blockDim.x + threadIdx.x;
    if (i < NN) deg[i] = 0;
    if (i < 384) stats[i] = 0.0f;
    if (i < NGR * 64) pool[i] = 0.0f;
    if (i < NGR) gcnt[i] = 0;
}

__global__ void k_hist(const int* __restrict__ ei, int* __restrict__ deg) {
    int e = blockIdx.x * blockDim.x + threadIdx.x;
    if (e < NE) atomicAdd(&deg[ei[NE + e]], 1);
}

__global__ void k_gcnt(const int* __restrict__ batch, int* __restrict__ gcnt) {
    int n = blockIdx.x * blockDim.x + threadIdx.x;
    if (n < NN) atomicAdd(&gcnt[batch[n]], 1);
}

__global__ void k_scan(const int* __restrict__ deg, int* __restrict__ rowptr,
                       int* __restrict__ cursor) {
    __shared__ int part[1024];
    const int t = threadIdx.x;
    const int CH = (NN + 1023) / 1024;             // 49
    int start = t * CH;
    int end = start + CH; if (end > NN) end = NN;
    int s = 0;
    for (int i = start; i < end; i++) s += deg[i];
    part[t] = s;
    __syncthreads();
    for (int off = 1; off < 1024; off <<= 1) {
        int v = part[t];
        int add = (t >= off) ? part[t - off] : 0;
        __syncthreads();
        part[t] = v + add;
        __syncthreads();
    }
    int run = (t > 0) ? part[t - 1] : 0;
    for (int i = start; i < end; i++) {
        rowptr[i] = run;
        cursor[i] = run;
        run += deg[i];
    }
    if (t == 1023) rowptr[NN] = run;
}

__global__ void k_fill(const int* __restrict__ ei, int* __restrict__ cursor,
                       int* __restrict__ csr) {
    int e = blockIdx.x * blockDim.x + threadIdx.x;
    if (e >= NE) return;
    int pos = atomicAdd(&cursor[ei[NE + e]], 1);
    csr[pos] = ei[e];
}

// pull-gather (fp32) with fused BN of the PREVIOUS layer (exact algebra):
//   out[n] = sc * (h[n] + sum_{s in N(n)} h[s]) + (deg(n)+1) * sh
__global__ void k_gather_bn(const float4* __restrict__ h,
                            const int* __restrict__ rowptr,
                            const int* __restrict__ csr,
                            const float* __restrict__ stats,
                            const float* __restrict__ gamma,
                            const float* __restrict__ beta,
                            float4* __restrict__ out) {
    __shared__ float sc[64], sh[64];
    const int t = threadIdx.x;
    if (stats != nullptr) {
        if (t < 64) {
            float mean = stats[t] * (1.0f / NN);
            float var  = stats[64 + t] * (1.0f / NN) - mean * mean;
            float s = gamma[t] * rsqrtf(var + BN_EPS);
            sc[t] = s;
            sh[t] = beta[t] - mean * s;
        }
        __syncthreads();
    }
    int i = blockIdx.x * blockDim.x + t;
    if (i >= NN * 16) return;
    int n = i >> 4;
    int j = i & 15;
    int b = rowptr[n], e = rowptr[n + 1];

    float4 a0 = h[n * 16 + j];
    float4 a1 = make_float4(0.f, 0.f, 0.f, 0.f);
    float4 a2 = a1, a3 = a1;

    int idx = b;
    while (idx < e && (idx & 3)) {                 // peel to 16B alignment of csr
        f4add(a0, h[__ldg(&csr[idx]) * 16 + j]);
        idx++;
    }
    for (; idx + 4 <= e; idx += 4) {
        int4 s4 = *(const int4*)&csr[idx];         // broadcast across slice threads
        float4 v0 = h[s4.x * 16 + j];
        float4 v1 = h[s4.y * 16 + j];
        float4 v2 = h[s4.z * 16 + j];
        float4 v3 = h[s4.w * 16 + j];
        f4add(a0, v0); f4add(a1, v1); f4add(a2, v2); f4add(a3, v3);
    }
    for (; idx < e; idx++) f4add(a0, h[__ldg(&csr[idx]) * 16 + j]);
    f4add(a0, a1); f4add(a2, a3); f4add(a0, a2);

    if (stats != nullptr) {
        float cnt = (float)(e - b + 1);
        int c = j * 4;
        a0.x = a0.x * sc[c + 0] + cnt * sh[c + 0];
        a0.y = a0.y * sc[c + 1] + cnt * sh[c + 1];
        a0.z = a0.z * sc[c + 2] + cnt * sh[c + 2];
        a0.w = a0.w * sc[c + 3] + cnt * sh[c + 3];
    }
    out[i] = a0;
}

// ---------------- fused MLP (R5/R6-proven 8x4 GEMM core) ----------------
// Epilogue: column stats (fp32-exact) always; then either store Z2 (layers 1-2)
// or atomically accumulate raw z into pool[batch[r]] (layer 3, BN applied later).
__global__ void __launch_bounds__(256) k_gin_mlp(
        const float* __restrict__ A,
        const float* __restrict__ Wa, const float* __restrict__ ba,
        const float* __restrict__ Wb, const float* __restrict__ bb,
        float* __restrict__ Z2, float* __restrict__ stats,
        const int* __restrict__ batch, float* __restrict__ pool, int rows) {
    __shared__ float As[128][68];
    __shared__ float4 Wc[16][64];
    __shared__ float s_sum[64], s_sq[64], sbias_a[64], sbias_b[64];

    const int t = threadIdx.x;
    const int tx = t & 15;
    const int ty = t >> 4;
    const int rb = ty * 8;
    const int row0 = blockIdx.x * 128;

    for (int i = t; i < 1024; i += 256) {
        int kk = i >> 6, c = i & 63;
        Wc[kk][c] = make_float4(Wa[(4 * kk + 0) * 64 + c], Wa[(4 * kk + 1) * 64 + c],
                                Wa[(4 * kk + 2) * 64 + c], Wa[(4 * kk + 3) * 64 + c]);
    }
    for (int i = t; i < 2048; i += 256) {
        int r = i >> 4, kc = i & 15;
        float4 v = make_float4(0.f, 0.f, 0.f, 0.f);
        if (row0 + r < rows) v = ((const float4*)A)[(row0 + r) * 16 + kc];
        *(float4*)&As[r][kc * 4] = v;
    }
    if (t < 64) { s_sum[t] = 0.f; s_sq[t] = 0.f; sbias_a[t] = ba[t]; sbias_b[t] = bb[t]; }
    __syncthreads();

    unsigned long long acc[8][4];
#pragma unroll
    for (int i = 0; i < 8; i++)
#pragma unroll
        for (int j = 0; j < 4; j++) acc[i][j] = 0ull;

#pragma unroll 4
    for (int kk = 0; kk < 16; kk++) {
        ulonglong2 w[4];
#pragma unroll
        for (int j = 0; j < 4; j++)
            w[j] = *(const ulonglong2*)&Wc[kk][tx + 16 * j];
#pragma unroll
        for (int i = 0; i < 8; i++) {
            ulonglong2 a = *(const ulonglong2*)&As[rb + i][kk * 4];
#pragma unroll
            for (int j = 0; j < 4; j++) {
                fma2(acc[i][j], a.x, w[j].x);
                fma2(acc[i][j], a.y, w[j].y);
            }
        }
    }
    __syncthreads();

#pragma unroll
    for (int i = 0; i < 8; i++) {
#pragma unroll
        for (int j = 0; j < 4; j++) {
            int c = tx + 16 * j;
            float v = fmaxf(fma2_reduce(acc[i][j]) + sbias_a[c], 0.f);
            As[rb + i][c] = v;
            acc[i][j] = 0ull;
        }
    }
    for (int i = t; i < 1024; i += 256) {
        int kk = i >> 6, c = i & 63;
        Wc[kk][c] = make_float4(Wb[(4 * kk + 0) * 64 + c], Wb[(4 * kk + 1) * 64 + c],
                                Wb[(4 * kk + 2) * 64 + c], Wb[(4 * kk + 3) * 64 + c]);
    }
    __syncthreads();

#pragma unroll 4
    for (int kk = 0; kk < 16; kk++) {
        ulonglong2 w[4];
#pragma unroll
        for (int j = 0; j < 4; j++)
            w[j] = *(const ulonglong2*)&Wc[kk][tx + 16 * j];
#pragma unroll
        for (int i = 0; i < 8; i++) {
            ulonglong2 a = *(const ulonglong2*)&As[rb + i][kk * 4];
#pragma unroll
            for (int j = 0; j < 4; j++) {
                fma2(acc[i][j], a.x, w[j].x);
                fma2(acc[i][j], a.y, w[j].y);
            }
        }
    }

    float s[4] = {0.f, 0.f, 0.f, 0.f};
    float q[4] = {0.f, 0.f, 0.f, 0.f};
#pragma unroll
    for (int i = 0; i < 8; i++) {
        int r = row0 + rb + i;
        if (r < rows) {
            int gbase = pool ? (batch[r] * 64) : 0;
#pragma unroll
            for (int j = 0; j < 4; j++) {
                int c = tx + 16 * j;
                float v = fmaxf(fma2_reduce(acc[i][j]) + sbias_b[c], 0.f);
                if (pool) atomicAdd(&pool[gbase + c], v);
                else      Z2[r * 64 + c] = v;
                s[j] += v;
                q[j] += v * v;
            }
        }
    }
#pragma unroll
    for (int j = 0; j < 4; j++) {
        s[j] += __shfl_down_sync(0xffffffff, s[j], 16);
        q[j] += __shfl_down_sync(0xffffffff, q[j], 16);
    }
    if ((t & 31) < 16) {
#pragma unroll
        for (int j = 0; j < 4; j++) {
            atomicAdd(&s_sum[tx + 16 * j], s[j]);
            atomicAdd(&s_sq[tx + 16 * j], q[j]);
        }
    }
    __syncthreads();
    if (t < 64) {
        atomicAdd(&stats[t], s_sum[t]);
        atomicAdd(&stats[64 + t], s_sq[t]);
    }
}

// ---------------- fused head: BN3 affine on pooled raw z, then lin0+fc1+relu ----
// pool_bn[g][c] = sc[c]*pool_raw[g][c] + cnt_g*sh[c]   (exact rearrangement)
__global__ void __launch_bounds__(128) k_head(
        const float* __restrict__ pool, const int* __restrict__ gcnt,
        const float* __restrict__ stats,
        const float* __restrict__ gamma, const float* __restrict__ beta,
        const float* __restrict__ w_lin0, const float* __restrict__ b_lin0,
        const float* __restrict__ w_fc1,  const float* __restrict__ b_fc1,
        float* __restrict__ out) {
    __shared__ float p[64], mid[128];
    int g = blockIdx.x;
    int t = threadIdx.x;
    if (t < 64) {
        float mean = stats[t] * (1.0f / NN);
        float var  = stats[64 + t] * (1.0f / NN) - mean * mean;
        float s = gamma[t] * rsqrtf(var + BN_EPS);
        float shv = beta[t] - mean * s;
        p[t] = pool[g * 64 + t] * s + (float)gcnt[g] * shv;
    }
    __syncthreads();
    {   // mid[t] = p . w_lin0[:, t]  (K=64, M=128)
        float acc = b_lin0[t];
#pragma unroll 8
        for (int k = 0; k < 64; k++) acc += p[k] * w_lin0[k * 128 + t];
        mid[t] = acc;
    }
    __syncthreads();
    if (t < 64) {   // out[t] = relu(mid . w_fc1[:, t])  (K=128, M=64)
        float acc = b_fc1[t];
#pragma unroll 8
        for (int k = 0; k < 128; k++) acc += mid[k] * w_fc1[k * 64 + t];
        out[g * 64 + t] = fmaxf(acc, 0.f);
    }
}

// ---------------- launch ----------------

extern "C" void kernel_launch(void* const* d_in, const int* in_sizes, int n_in,
                              void* d_out, int out_size) {
    const float* x     = (const float*)d_in[0];
    const int*   ei    = (const int*)d_in[1];
    const int*   batch = (const int*)d_in[2];
    const float* prm[22];
    for (int i = 0; i < 22; i++) prm[i] = (const float*)d_in[3 + i];
    // per layer L at 6L: w_a,b_a,w_b,b_b,gamma,beta ; 18..21: w_lin0,b_lin0,w_fc1,b_fc1

    float *agg, *z2, *stats, *pool;
    int *deg, *rowptr, *cursor, *csr, *gcnt;
    cudaGetSymbolAddress((void**)&agg,    g_agg);
    cudaGetSymbolAddress((void**)&z2,     g_z2);
    cudaGetSymbolAddress((void**)&stats,  g_stats);
    cudaGetSymbolAddress((void**)&pool,   g_pool);
    cudaGetSymbolAddress((void**)&gcnt,   g_gcnt);
    cudaGetSymbolAddress((void**)&deg,    g_deg);
    cudaGetSymbolAddress((void**)&rowptr, g_rowptr);
    cudaGetSymbolAddress((void**)&cursor, g_cursor);
    cudaGetSymbolAddress((void**)&csr,    g_csr);

    const int MLP_BLOCKS = (NN + 127) / 128;
    const int EDG_BLOCKS = (NE + 255) / 256;
    const int NOD_BLOCKS = (NN * 16 + 255) / 256;

    // -------- CSR build + per-graph node counts --------
    k_init<<<(NN + 255) / 256, 256>>>(deg, stats, pool, gcnt);
    k_hist<<<EDG_BLOCKS, 256>>>(ei, deg);
    k_gcnt<<<(NN + 255) / 256, 256>>>(batch, gcnt);
    k_scan<<<1, 1024>>>(deg, rowptr, cursor);
    k_fill<<<EDG_BLOCKS, 256>>>(ei, cursor, csr);

    // -------- layer 1 (raw x) --------
    k_gather_bn<<<NOD_BLOCKS, 256>>>((const float4*)x, rowptr, csr,
                                     nullptr, nullptr, nullptr, (float4*)agg);
    k_gin_mlp<<<MLP_BLOCKS, 256>>>(agg, prm[0], prm[1], prm[2], prm[3],
                                   z2, stats, nullptr, nullptr, NN);

    // -------- layer 2 (gather applies BN1) --------
    k_gather_bn<<<NOD_BLOCKS, 256>>>((const float4*)z2, rowptr, csr,
                                     stats, prm[4], prm[5], (float4*)agg);
    k_gin_mlp<<<MLP_BLOCKS, 256>>>(agg, prm[6], prm[7], prm[8], prm[9],
                                   z2, stats + 128, nullptr, nullptr, NN);

    // -------- layer 3 (gather applies BN2; epilogue pools raw z directly) --------
    k_gather_bn<<<NOD_BLOCKS, 256>>>((const float4*)z2, rowptr, csr,
                                     stats + 128, prm[10], prm[11], (float4*)agg);
    k_gin_mlp<<<MLP_BLOCKS, 256>>>(agg, prm[12], prm[13], prm[14], prm[15],
                                   nullptr, stats + 256, batch, pool, NN);

    // -------- head (applies BN3 affine to pooled sums, then lin0+fc1+relu) ----
    k_head<<<NGR, 128>>>(pool, gcnt, stats + 256, prm[16], prm[17],
                         prm[18], prm[19], prm[20], prm[21], (float*)d_out);
}

// round 17
// speedup vs baseline: 1.3356x; 1.3356x over previous
#include <cuda_runtime.h>
#include <cstdint>

#define NN 50000
#define NE 800000
#define NGR 512
#define BN_EPS 1e-5f
#define SCAN_NBLK ((NN + 255) / 256)   // 196

// ---------------- scratch (static __device__ — no allocations) ----------------
__device__ float4 g_agg[NN * 16];
__device__ float4 g_z2 [NN * 16];
__device__ float  g_stats[384];          // 3 layers x (sum[64], sumsq[64])
__device__ float  g_pool[NGR * 64];      // raw z pool (pre-BN3)
__device__ int    g_gcnt[NGR];           // nodes per graph
__device__ int    g_deg[NN];
__device__ int    g_rowptr[NN + 1];
__device__ int    g_cursor[NN];
__device__ int    g_csr[NE];
__device__ int    g_bsum[256];           // block partial sums for scan

// packed fp32x2 FMA (Blackwell family-level instruction, not an 'a' feature)
__device__ __forceinline__ void fma2(unsigned long long& acc,
                                     unsigned long long a,
                                     unsigned long long b) {
    asm("fma.rn.f32x2 %0, %1, %2, %0;" : "+l"(acc) : "l"(a), "l"(b));
}
__device__ __forceinline__ float fma2_reduce(unsigned long long acc) {
    float lo = __uint_as_float((uint32_t)acc);
    float hi = __uint_as_float((uint32_t)(acc >> 32));
    return lo + hi;
}
__device__ __forceinline__ void f4add(float4& a, float4 b) {
    a.x += b.x; a.y += b.y; a.z += b.z; a.w += b.w;
}

// ---------------- CSR build ----------------

__global__ void k_init(int* __restrict__ deg, float* __restrict__ stats,
                       float* __restrict__ pool, int* __restrict__ gcnt) {
    int i = blockIdx.x * blockDim.x + threadIdx.x;
    if (i < NN) deg[i] = 0;
    if (i < 384) stats[i] = 0.0f;
    if (i < NGR * 64) pool[i] = 0.0f;
    if (i < NGR) gcnt[i] = 0;
}

__global__ void k_hist(const int* __restrict__ ei, int* __restrict__ deg) {
    int e = blockIdx.x * blockDim.x + threadIdx.x;
    if (e < NE) atomicAdd(&deg[ei[NE + e]], 1);
}

__global__ void k_gcnt(const int* __restrict__ batch, int* __restrict__ gcnt) {
    int n = blockIdx.x * blockDim.x + threadIdx.x;
    if (n < NN) atomicAdd(&gcnt[batch[n]], 1);
}

// ---- parallel exclusive scan of deg -> rowptr/cursor (3 passes) ----

// pass 1: per-block sums (196 blocks x 256)
__global__ void k_bsum(const int* __restrict__ deg, int* __restrict__ bsum) {
    __shared__ int sh[256];
    int t = threadIdx.x;
    int i = blockIdx.x * 256 + t;
    sh[t] = (i < NN) ? deg[i] : 0;
    __syncthreads();
#pragma unroll
    for (int off = 128; off > 0; off >>= 1) {
        if (t < off) sh[t] += sh[t + off];
        __syncthreads();
    }
    if (t == 0) bsum[blockIdx.x] = sh[0];
}

// pass 2: exclusive scan of the 196 block sums (1 block, 256 threads)
__global__ void k_bscan(int* __restrict__ bsum, int nb) {
    __shared__ int sh[256];
    int t = threadIdx.x;
    sh[t] = (t < nb) ? bsum[t] : 0;
    __syncthreads();
#pragma unroll
    for (int off = 1; off < 256; off <<= 1) {
        int v = sh[t];
        int add = (t >= off) ? sh[t - off] : 0;
        __syncthreads();
        sh[t] = v + add;
        __syncthreads();
    }
    if (t < nb) bsum[t] = (t > 0) ? sh[t - 1] : 0;   // exclusive
}

// pass 3: per-block exclusive scan + base offset -> rowptr/cursor
__global__ void k_scan2(const int* __restrict__ deg, const int* __restrict__ bsum,
                        int* __restrict__ rowptr, int* __restrict__ cursor) {
    __shared__ int sh[256];
    int t = threadIdx.x;
    int i = blockIdx.x * 256 + t;
    int v = (i < NN) ? deg[i] : 0;
    sh[t] = v;
    __syncthreads();
#pragma unroll
    for (int off = 1; off < 256; off <<= 1) {
        int x = sh[t];
        int add = (t >= off) ? sh[t - off] : 0;
        __syncthreads();
        sh[t] = x + add;
        __syncthreads();
    }
    int incl = sh[t];
    int base = bsum[blockIdx.x];
    if (i < NN) {
        int excl = base + incl - v;
        rowptr[i] = excl;
        cursor[i] = excl;
        if (i == NN - 1) rowptr[NN] = base + incl;   // == NE
    }
}

__global__ void k_fill(const int* __restrict__ ei, int* __restrict__ cursor,
                       int* __restrict__ csr) {
    int e = blockIdx.x * blockDim.x + threadIdx.x;
    if (e >= NE) return;
    int pos = atomicAdd(&cursor[ei[NE + e]], 1);
    csr[pos] = ei[e];
}

// pull-gather (fp32) with fused BN of the PREVIOUS layer (exact algebra):
//   out[n] = sc * (h[n] + sum_{s in N(n)} h[s]) + (deg(n)+1) * sh
__global__ void k_gather_bn(const float4* __restrict__ h,
                            const int* __restrict__ rowptr,
                            const int* __restrict__ csr,
                            const float* __restrict__ stats,
                            const float* __restrict__ gamma,
                            const float* __restrict__ beta,
                            float4* __restrict__ out) {
    __shared__ float sc[64], sh[64];
    const int t = threadIdx.x;
    if (stats != nullptr) {
        if (t < 64) {
            float mean = stats[t] * (1.0f / NN);
            float var  = stats[64 + t] * (1.0f / NN) - mean * mean;
            float s = gamma[t] * rsqrtf(var + BN_EPS);
            sc[t] = s;
            sh[t] = beta[t] - mean * s;
        }
        __syncthreads();
    }
    int i = blockIdx.x * blockDim.x + t;
    if (i >= NN * 16) return;
    int n = i >> 4;
    int j = i & 15;
    int b = rowptr[n], e = rowptr[n + 1];

    float4 a0 = h[n * 16 + j];
    float4 a1 = make_float4(0.f, 0.f, 0.f, 0.f);
    float4 a2 = a1, a3 = a1;

    int idx = b;
    while (idx < e && (idx & 3)) {                 // peel to 16B alignment of csr
        f4add(a0, h[__ldg(&csr[idx]) * 16 + j]);
        idx++;
    }
    for (; idx + 4 <= e; idx += 4) {
        int4 s4 = *(const int4*)&csr[idx];         // broadcast across slice threads
        float4 v0 = h[s4.x * 16 + j];
        float4 v1 = h[s4.y * 16 + j];
        float4 v2 = h[s4.z * 16 + j];
        float4 v3 = h[s4.w * 16 + j];
        f4add(a0, v0); f4add(a1, v1); f4add(a2, v2); f4add(a3, v3);
    }
    for (; idx < e; idx++) f4add(a0, h[__ldg(&csr[idx]) * 16 + j]);
    f4add(a0, a1); f4add(a2, a3); f4add(a0, a2);

    if (stats != nullptr) {
        float cnt = (float)(e - b + 1);
        int c = j * 4;
        a0.x = a0.x * sc[c + 0] + cnt * sh[c + 0];
        a0.y = a0.y * sc[c + 1] + cnt * sh[c + 1];
        a0.z = a0.z * sc[c + 2] + cnt * sh[c + 2];
        a0.w = a0.w * sc[c + 3] + cnt * sh[c + 3];
    }
    out[i] = a0;
}

// ---------------- fused MLP (R5/R6-proven 8x4 GEMM core) ----------------
// Epilogue: column stats (fp32-exact) always; then either store Z2 (layers 1-2)
// or atomically accumulate raw z into pool[batch[r]] (layer 3, BN applied later).
__global__ void __launch_bounds__(256) k_gin_mlp(
        const float* __restrict__ A,
        const float* __restrict__ Wa, const float* __restrict__ ba,
        const float* __restrict__ Wb, const float* __restrict__ bb,
        float* __restrict__ Z2, float* __restrict__ stats,
        const int* __restrict__ batch, float* __restrict__ pool, int rows) {
    __shared__ float As[128][68];
    __shared__ float4 Wc[16][64];
    __shared__ float s_sum[64], s_sq[64], sbias_a[64], sbias_b[64];

    const int t = threadIdx.x;
    const int tx = t & 15;
    const int ty = t >> 4;
    const int rb = ty * 8;
    const int row0 = blockIdx.x * 128;

    for (int i = t; i < 1024; i += 256) {
        int kk = i >> 6, c = i & 63;
        Wc[kk][c] = make_float4(Wa[(4 * kk + 0) * 64 + c], Wa[(4 * kk + 1) * 64 + c],
                                Wa[(4 * kk + 2) * 64 + c], Wa[(4 * kk + 3) * 64 + c]);
    }
    for (int i = t; i < 2048; i += 256) {
        int r = i >> 4, kc = i & 15;
        float4 v = make_float4(0.f, 0.f, 0.f, 0.f);
        if (row0 + r < rows) v = ((const float4*)A)[(row0 + r) * 16 + kc];
        *(float4*)&As[r][kc * 4] = v;
    }
    if (t < 64) { s_sum[t] = 0.f; s_sq[t] = 0.f; sbias_a[t] = ba[t]; sbias_b[t] = bb[t]; }
    __syncthreads();

    unsigned long long acc[8][4];
#pragma unroll
    for (int i = 0; i < 8; i++)
#pragma unroll
        for (int j = 0; j < 4; j++) acc[i][j] = 0ull;

#pragma unroll 4
    for (int kk = 0; kk < 16; kk++) {
        ulonglong2 w[4];
#pragma unroll
        for (int j = 0; j < 4; j++)
            w[j] = *(const ulonglong2*)&Wc[kk][tx + 16 * j];
#pragma unroll
        for (int i = 0; i < 8; i++) {
            ulonglong2 a = *(const ulonglong2*)&As[rb + i][kk * 4];
#pragma unroll
            for (int j = 0; j < 4; j++) {
                fma2(acc[i][j], a.x, w[j].x);
                fma2(acc[i][j], a.y, w[j].y);
            }
        }
    }
    __syncthreads();

#pragma unroll
    for (int i = 0; i < 8; i++) {
#pragma unroll
        for (int j = 0; j < 4; j++) {
            int c = tx + 16 * j;
            float v = fmaxf(fma2_reduce(acc[i][j]) + sbias_a[c], 0.f);
            As[rb + i][c] = v;
            acc[i][j] = 0ull;
        }
    }
    for (int i = t; i < 1024; i += 256) {
        int kk = i >> 6, c = i & 63;
        Wc[kk][c] = make_float4(Wb[(4 * kk + 0) * 64 + c], Wb[(4 * kk + 1) * 64 + c],
                                Wb[(4 * kk + 2) * 64 + c], Wb[(4 * kk + 3) * 64 + c]);
    }
    __syncthreads();

#pragma unroll 4
    for (int kk = 0; kk < 16; kk++) {
        ulonglong2 w[4];
#pragma unroll
        for (int j = 0; j < 4; j++)
            w[j] = *(const ulonglong2*)&Wc[kk][tx + 16 * j];
#pragma unroll
        for (int i = 0; i < 8; i++) {
            ulonglong2 a = *(const ulonglong2*)&As[rb + i][kk * 4];
#pragma unroll
            for (int j = 0; j < 4; j++) {
                fma2(acc[i][j], a.x, w[j].x);
                fma2(acc[i][j], a.y, w[j].y);
            }
        }
    }

    float s[4] = {0.f, 0.f, 0.f, 0.f};
    float q[4] = {0.f, 0.f, 0.f, 0.f};
#pragma unroll
    for (int i = 0; i < 8; i++) {
        int r = row0 + rb + i;
        if (r < rows) {
            int gbase = pool ? (batch[r] * 64) : 0;
#pragma unroll
            for (int j = 0; j < 4; j++) {
                int c = tx + 16 * j;
                float v = fmaxf(fma2_reduce(acc[i][j]) + sbias_b[c], 0.f);
                if (pool) atomicAdd(&pool[gbase + c], v);
                else      Z2[r * 64 + c] = v;
                s[j] += v;
                q[j] += v * v;
            }
        }
    }
#pragma unroll
    for (int j = 0; j < 4; j++) {
        s[j] += __shfl_down_sync(0xffffffff, s[j], 16);
        q[j] += __shfl_down_sync(0xffffffff, q[j], 16);
    }
    if ((t & 31) < 16) {
#pragma unroll
        for (int j = 0; j < 4; j++) {
            atomicAdd(&s_sum[tx + 16 * j], s[j]);
            atomicAdd(&s_sq[tx + 16 * j], q[j]);
        }
    }
    __syncthreads();
    if (t < 64) {
        atomicAdd(&stats[t], s_sum[t]);
        atomicAdd(&stats[64 + t], s_sq[t]);
    }
}

// ---------------- fused head: BN3 affine on pooled raw z, then lin0+fc1+relu ----
// pool_bn[g][c] = sc[c]*pool_raw[g][c] + cnt_g*sh[c]   (exact rearrangement)
__global__ void __launch_bounds__(128) k_head(
        const float* __restrict__ pool, const int* __restrict__ gcnt,
        const float* __restrict__ stats,
        const float* __restrict__ gamma, const float* __restrict__ beta,
        const float* __restrict__ w_lin0, const float* __restrict__ b_lin0,
        const float* __restrict__ w_fc1,  const float* __restrict__ b_fc1,
        float* __restrict__ out) {
    __shared__ float p[64], mid[128];
    int g = blockIdx.x;
    int t = threadIdx.x;
    if (t < 64) {
        float mean = stats[t] * (1.0f / NN);
        float var  = stats[64 + t] * (1.0f / NN) - mean * mean;
        float s = gamma[t] * rsqrtf(var + BN_EPS);
        float shv = beta[t] - mean * s;
        p[t] = pool[g * 64 + t] * s + (float)gcnt[g] * shv;
    }
    __syncthreads();
    {   // mid[t] = p . w_lin0[:, t]  (K=64, M=128)
        float acc = b_lin0[t];
#pragma unroll 8
        for (int k = 0; k < 64; k++) acc += p[k] * w_lin0[k * 128 + t];
        mid[t] = acc;
    }
    __syncthreads();
    if (t < 64) {   // out[t] = relu(mid . w_fc1[:, t])  (K=128, M=64)
        float acc = b_fc1[t];
#pragma unroll 8
        for (int k = 0; k < 128; k++) acc += mid[k] * w_fc1[k * 64 + t];
        out[g * 64 + t] = fmaxf(acc, 0.f);
    }
}

// ---------------- launch ----------------

extern "C" void kernel_launch(void* const* d_in, const int* in_sizes, int n_in,
                              void* d_out, int out_size) {
    const float* x     = (const float*)d_in[0];
    const int*   ei    = (const int*)d_in[1];
    const int*   batch = (const int*)d_in[2];
    const float* prm[22];
    for (int i = 0; i < 22; i++) prm[i] = (const float*)d_in[3 + i];
    // per layer L at 6L: w_a,b_a,w_b,b_b,gamma,beta ; 18..21: w_lin0,b_lin0,w_fc1,b_fc1

    float *agg, *z2, *stats, *pool;
    int *deg, *rowptr, *cursor, *csr, *gcnt, *bsum;
    cudaGetSymbolAddress((void**)&agg,    g_agg);
    cudaGetSymbolAddress((void**)&z2,     g_z2);
    cudaGetSymbolAddress((void**)&stats,  g_stats);
    cudaGetSymbolAddress((void**)&pool,   g_pool);
    cudaGetSymbolAddress((void**)&gcnt,   g_gcnt);
    cudaGetSymbolAddress((void**)&deg,    g_deg);
    cudaGetSymbolAddress((void**)&rowptr, g_rowptr);
    cudaGetSymbolAddress((void**)&cursor, g_cursor);
    cudaGetSymbolAddress((void**)&csr,    g_csr);
    cudaGetSymbolAddress((void**)&bsum,   g_bsum);

    const int MLP_BLOCKS = (NN + 127) / 128;
    const int EDG_BLOCKS = (NE + 255) / 256;
    const int NOD_BLOCKS = (NN * 16 + 255) / 256;

    // -------- CSR build + per-graph node counts (parallel 3-pass scan) --------
    k_init<<<(NN + 255) / 256, 256>>>(deg, stats, pool, gcnt);
    k_hist<<<EDG_BLOCKS, 256>>>(ei, deg);
    k_gcnt<<<(NN + 255) / 256, 256>>>(batch, gcnt);
    k_bsum<<<SCAN_NBLK, 256>>>(deg, bsum);
    k_bscan<<<1, 256>>>(bsum, SCAN_NBLK);
    k_scan2<<<SCAN_NBLK, 256>>>(deg, bsum, rowptr, cursor);
    k_fill<<<EDG_BLOCKS, 256>>>(ei, cursor, csr);

    // -------- layer 1 (raw x) --------
    k_gather_bn<<<NOD_BLOCKS, 256>>>((const float4*)x, rowptr, csr,
                                     nullptr, nullptr, nullptr, (float4*)agg);
    k_gin_mlp<<<MLP_BLOCKS, 256>>>(agg, prm[0], prm[1], prm[2], prm[3],
                                   z2, stats, nullptr, nullptr, NN);

    // -------- layer 2 (gather applies BN1) --------
    k_gather_bn<<<NOD_BLOCKS, 256>>>((const float4*)z2, rowptr, csr,
                                     stats, prm[4], prm[5], (float4*)agg);
    k_gin_mlp<<<MLP_BLOCKS, 256>>>(agg, prm[6], prm[7], prm[8], prm[9],
                                   z2, stats + 128, nullptr, nullptr, NN);

    // -------- layer 3 (gather applies BN2; epilogue pools raw z directly) --------
    k_gather_bn<<<NOD_BLOCKS, 256>>>((const float4*)z2, rowptr, csr,
                                     stats + 128, prm[10], prm[11], (float4*)agg);
    k_gin_mlp<<<MLP_BLOCKS, 256>>>(agg, prm[12], prm[13], prm[14], prm[15],
                                   nullptr, stats + 256, batch, pool, NN);

    // -------- head (applies BN3 affine to pooled sums, then lin0+fc1+relu) ----
    k_head<<<NGR, 128>>>(pool, gcnt, stats + 256, prm[16], prm[17],
                         prm[18], prm[19], prm[20], prm[21], (float*)d_out);
}